// round 5
// baseline (speedup 1.0000x reference)
#include <cuda_runtime.h>
#include <stdint.h>

#define HH 512
#define WW 512
#define NB 4

typedef unsigned long long ull;

// Packed border tensor: 16 channels x 2 bits per pixel (values in {0,1,2}).
__device__ uint32_t g_border[NB * HH * WW];

__device__ __forceinline__ ull ffma2(ull a, ull b, ull c) {
    ull d;
    asm("fma.rn.f32x2 %0, %1, %2, %3;" : "=l"(d) : "l"(a), "l"(b), "l"(c));
    return d;
}
__device__ __forceinline__ ull pack2(float x, float y) {
    ull d;
    asm("mov.b64 %0, {%1, %2};" : "=l"(d) : "f"(x), "f"(y));
    return d;
}
__device__ __forceinline__ float2 unpack2(ull v) {
    float2 r;
    asm("mov.b64 {%0, %1}, %2;" : "=f"(r.x), "=f"(r.y) : "l"(v));
    return r;
}
// Expand packed (bf16_a | bf16_b<<16) into f32x2 {a, b}: pure LOP/SHF, no CVT.
__device__ __forceinline__ ull bfexp(uint32_t u) {
    uint32_t lo = u << 16;
    uint32_t hi = u & 0xFFFF0000u;
    ull d;
    asm("mov.b64 %0, {%1, %2};" : "=l"(d) : "r"(lo), "r"(hi));
    return d;
}

// ---------------------------------------------------------------------------
// Stage 1: 11x11 conv (1->8 ch) on both input planes + spike/WTA logic.
// Planes (in0,in1) ride in one FFMA2. Duplicated weights stored [tap][filter]
// so each tap's 8 weights come from 4 broadcast LDS.128.
// Block (32,16), tile 32x32. Also zeroes d_out (stage2 accumulates via atomics).
// ---------------------------------------------------------------------------
__global__ __launch_bounds__(512)
void stage1_kernel(const float* __restrict__ inp, const float* __restrict__ Wb,
                   float* __restrict__ out)
{
    __shared__ ull s01[42][44];                  // (in0,in1) packed (14.8 KB)
    __shared__ __align__(16) ull dsh[121 * 8];   // dup weights [t][f] (7.7 KB)

    const int b  = blockIdx.z;
    const int x0 = blockIdx.x * 32;
    const int y0 = blockIdx.y * 32;
    const int tx = threadIdx.x;      // 0..31
    const int ty = threadIdx.y;      // 0..15
    const int tid = ty * 32 + tx;

    for (int i = tid; i < 968; i += 512) {
        int t = i >> 3, f = i & 7;
        float w = Wb[f * 121 + t];
        dsh[i] = pack2(w, w);
    }

    const float* __restrict__ in0 = inp + ((size_t)b * 2 + 0) * HH * WW;
    const float* __restrict__ in1 = inp + ((size_t)b * 2 + 1) * HH * WW;

    for (int ry = ty; ry < 42; ry += 16) {
        int gy = y0 - 5 + ry;
        for (int rx = tx; rx < 42; rx += 32) {
            int gx = x0 - 5 + rx;
            bool ok = ((unsigned)gy < HH) && ((unsigned)gx < WW);
            float v0 = ok ? in0[gy * WW + gx] : 0.0f;
            float v1 = ok ? in1[gy * WW + gx] : 0.0f;
            s01[ry][rx] = pack2(v0, v1);
        }
    }
    __syncthreads();

    ull acc0[8], acc1[8];            // .x = pos conv, .y = neg conv
    #pragma unroll
    for (int f = 0; f < 8; ++f) { acc0[f] = 0ull; acc1[f] = 0ull; }

    #pragma unroll 1
    for (int dy = 0; dy < 11; ++dy) {
        #pragma unroll
        for (int dx = 0; dx < 11; ++dx) {
            ull xa = s01[ty + dy][tx + dx];
            ull xb = s01[ty + 16 + dy][tx + dx];
            const int t = dy * 11 + dx;
            const ulonglong2* wp = (const ulonglong2*)&dsh[t * 8];
            #pragma unroll
            for (int fp = 0; fp < 4; ++fp) {
                ulonglong2 w2 = wp[fp];
                acc0[2*fp]   = ffma2(w2.x, xa, acc0[2*fp]);
                acc1[2*fp]   = ffma2(w2.x, xb, acc1[2*fp]);
                acc0[2*fp+1] = ffma2(w2.y, xa, acc0[2*fp+1]);
                acc1[2*fp+1] = ffma2(w2.y, xb, acc1[2*fp+1]);
            }
        }
    }

    #pragma unroll
    for (int k = 0; k < 2; ++k) {
        const int yy = ty + k * 16;
        float2 ctr = unpack2(s01[yy + 5][tx + 5]);
        float vm = ctr.x + ctr.y;

        int b13[4], b24[4];
        #pragma unroll
        for (int o = 0; o < 4; ++o) {
            float2 e = unpack2(k == 0 ? acc0[2*o]   : acc1[2*o]);
            float2 d = unpack2(k == 0 ? acc0[2*o+1] : acc1[2*o+1]);
            float pe = e.x >= 1.0f ? 1.0f : 0.0f;
            float ne = e.y >= 1.0f ? 1.0f : 0.0f;
            float po = d.x >= 1.0f ? 1.0f : 0.0f;
            float no = d.y >= 1.0f ? 1.0f : 0.0f;
            int s1 = (vm * (pe - 1.5f * no) >= 1.0f) ? 1 : 0;
            int s2 = (vm * (ne - 1.5f * po) >= 1.0f) ? 1 : 0;
            int s3 = (vm * (po - 1.5f * ne) >= 1.0f) ? 1 : 0;
            int s4 = (vm * (no - 1.5f * pe) >= 1.0f) ? 1 : 0;
            b13[o] = s1 + s2;
            b24[o] = s3 + s4;
        }

        int tmax = 0;
        #pragma unroll
        for (int o = 0; o < 4; ++o) {
            int d = b13[o] - b24[o];
            int tp = d < 0 ? -d : d;
            if (tp > tmax) tmax = tp;
        }

        uint32_t word = 0;
        #pragma unroll
        for (int o = 0; o < 4; ++o) {
            int d = b13[o] - b24[o];
            int tp = d < 0 ? -d : d;
            uint32_t nib = 0;
            if (tp == tmax) {
                if (d >= 1)
                    nib = (uint32_t)b13[o] | ((uint32_t)b24[o] << 2);
                else if (d <= -1)
                    nib = ((uint32_t)b24[o] << 4) | ((uint32_t)b13[o] << 6);
            }
            word |= nib << (8 * o);
        }
        const size_t pix = ((size_t)b * HH + (y0 + yy)) * WW + (x0 + tx);
        g_border[pix] = word;
        out[pix] = 0.0f;   // zero-init for stage2's atomic accumulation
    }
}

// ---------------------------------------------------------------------------
// Stage 2: depthwise 23x23 conv + spike combination. ONE (tile, group) per
// block; results combine via predicated atomicAdd. Block (32,2), tile 32x32,
// 16 output rows/thread with a 16-register rolling window.
// Tile stored as packed bf16x2 (exact for values {0,1,2}): halves smem
// (16.1 KB -> ~12 resident blocks) and halves data LDS wavefronts; expansion
// to f32x2 costs 2 LOPs on the alu pipe. Weights stay fp32 (exact math).
// ---------------------------------------------------------------------------
__global__ __launch_bounds__(64)
void stage2_kernel(const float* __restrict__ Wg, float* __restrict__ out)
{
    __shared__ uint32_t sh[54][55];   // packed bf16 pairs (11.9 KB)
    __shared__ ull wsh[529];          // duplicated fp32 weights (4.2 KB)

    const int zz  = blockIdx.z;          // 0..31 = b*8 + grp
    const int b   = zz >> 3;
    const int grp = zz & 7;
    const int x0 = blockIdx.x * 32;
    const int y0 = blockIdx.y * 32;
    const int tx = threadIdx.x;   // 0..31
    const int ty = threadIdx.y;   // 0..1
    const int tid = ty * 32 + tx;
    const int yb = ty * 16;

    const uint32_t* __restrict__ bor = g_border + (size_t)b * HH * WW;
    const int shift = grp * 4;

    for (int i = tid; i < 529; i += 64) {
        float w = Wg[grp * 2 * 529 + i];
        wsh[i] = pack2(w, w);
    }

    for (int ry = ty; ry < 54; ry += 2) {
        int gy = y0 - 11 + ry;
        for (int rx = tx; rx < 54; rx += 32) {
            int gx = x0 - 11 + rx;
            uint32_t v = 0;
            if (((unsigned)gy < HH) && ((unsigned)gx < WW)) v = bor[gy * WW + gx];
            uint32_t a = (v >> shift) & 3u;
            uint32_t bb = (v >> (shift + 2)) & 3u;
            // bf16 bits of small ints = top 16 bits of their f32 pattern
            uint32_t pa = __float_as_uint((float)a) >> 16;
            uint32_t pb = __float_as_uint((float)bb) & 0xFFFF0000u;
            sh[ry][rx] = pa | pb;
        }
    }
    __syncthreads();

    ull a[16];
    #pragma unroll
    for (int o = 0; o < 16; ++o) a[o] = 0ull;

    #pragma unroll 1
    for (int dx = 0; dx < 23; ++dx) {
        const int c = tx + dx;
        ull r[16];
        #pragma unroll
        for (int o = 0; o < 16; ++o) r[o] = bfexp(sh[yb + o][c]);

        #pragma unroll
        for (int dy = 0; dy < 23; ++dy) {
            ull w = wsh[dy * 23 + dx];
            #pragma unroll
            for (int o = 0; o < 16; ++o) a[o] = ffma2(w, r[o], a[o]);
            if (dy < 22) {
                #pragma unroll
                for (int o = 0; o < 15; ++o) r[o] = r[o + 1];
                r[15] = bfexp(sh[yb + dy + 16][c]);
            }
        }
    }

    #pragma unroll
    for (int o = 0; o < 16; ++o) {
        float2 v = unpack2(a[o]);
        if (v.x >= 1.0f && v.y < 1.0f)
            atomicAdd(&out[((size_t)b * HH + (y0 + yb + o)) * WW + x0 + tx], 1.0f);
    }
}

// ---------------------------------------------------------------------------
extern "C" void kernel_launch(void* const* d_in, const int* in_sizes, int n_in,
                              void* d_out, int out_size)
{
    const float* inp = nullptr;
    const float* Wb  = nullptr;
    const float* Wg  = nullptr;
    for (int i = 0; i < n_in; ++i) {
        if (in_sizes[i] == NB * 2 * HH * WW) inp = (const float*)d_in[i];
        else if (in_sizes[i] == 8 * 121)     Wb  = (const float*)d_in[i];
        else if (in_sizes[i] == 16 * 529)    Wg  = (const float*)d_in[i];
    }

    dim3 grid1(WW / 32, HH / 32, NB);
    dim3 blk1(32, 16);
    stage1_kernel<<<grid1, blk1>>>(inp, Wb, (float*)d_out);

    dim3 grid2(WW / 32, HH / 32, NB * 8);   // one (tile, group) per block
    dim3 blk2(32, 2);
    stage2_kernel<<<grid2, blk2>>>(Wg, (float*)d_out);
}